// round 1
// baseline (speedup 1.0000x reference)
#include <cuda_runtime.h>
#include <cuda_bf16.h>
#include <math.h>

// Problem constants
#define T_TOK 3072
#define HID 5120
#define NH 16
#define DN 128
#define DR 64
#define DQK 192       // DN + DR
#define DV 128
#define Q_RANK 1536
#define KV_RANK 512
#define KV_A_OUT (KV_RANK + DR)   // 576

// ---------------------------------------------------------------------------
// Scratch (allocation-free: __device__ globals)
// ---------------------------------------------------------------------------
__device__ float g_qa[T_TOK * Q_RANK];        // q_a (rmsnorm in place)
__device__ float g_latent[T_TOK * KV_A_OUT];  // hidden @ w_kv_a
__device__ float g_kvan[T_TOK * KV_RANK];     // rmsnorm(latent[:, :512])
__device__ float g_q[T_TOK * NH * DQK];       // q (rope + scale in place)
__device__ float g_kv[T_TOK * NH * (DN + DV)];// kv = kvan @ w_kv_b
__device__ float g_kpe[T_TOK * DR];           // roped k_pe
__device__ float g_attn[T_TOK * NH * DV];     // attention output

// ---------------------------------------------------------------------------
// SGEMM: C[M,N] = A[M,K] @ B[K,N], row-major fp32.
// 128x128 tile, BK=16, 256 threads, 8x8 per-thread register tile.
// M % 128 == 0, K % 16 == 0, N % 4 == 0 required (true for all our shapes).
// ---------------------------------------------------------------------------
#define BM 128
#define BN 128
#define BK 16

__global__ __launch_bounds__(256) void sgemm_kernel(
    const float* __restrict__ A, const float* __restrict__ B,
    float* __restrict__ C, int M, int N, int K)
{
    __shared__ float As[BK][BM];
    __shared__ float Bs[BK][BN];

    const int tid = threadIdx.x;
    const int ty = tid >> 4;        // 0..15
    const int tx = tid & 15;        // 0..15
    const int m0 = blockIdx.y * BM;
    const int n0 = blockIdx.x * BN;

    float acc[8][8];
#pragma unroll
    for (int i = 0; i < 8; i++)
#pragma unroll
        for (int j = 0; j < 8; j++) acc[i][j] = 0.f;

    // A tile: 128 rows x 16 cols = 512 float4; each thread loads 2
    const int arow  = tid >> 2;          // 0..63
    const int acol4 = (tid & 3) * 4;     // 0,4,8,12
    // B tile: 16 rows x 128 cols = 512 float4; each thread loads 2
    const int brow  = tid >> 5;          // 0..7
    const int bcol4 = (tid & 31) * 4;    // 0..124

    for (int k0 = 0; k0 < K; k0 += BK) {
#pragma unroll
        for (int i = 0; i < 2; i++) {
            int r = arow + i * 64;
            float4 v = *(const float4*)(A + (size_t)(m0 + r) * K + k0 + acol4);
            As[acol4 + 0][r] = v.x;
            As[acol4 + 1][r] = v.y;
            As[acol4 + 2][r] = v.z;
            As[acol4 + 3][r] = v.w;
        }
#pragma unroll
        for (int i = 0; i < 2; i++) {
            int r = brow + i * 8;
            int c = n0 + bcol4;
            float4 v = make_float4(0.f, 0.f, 0.f, 0.f);
            if (c < N) v = *(const float4*)(B + (size_t)(k0 + r) * N + c);
            *(float4*)(&Bs[r][bcol4]) = v;
        }
        __syncthreads();

#pragma unroll
        for (int k = 0; k < BK; k++) {
            float a[8], b[8];
            *(float4*)(a)     = *(const float4*)(&As[k][ty * 8]);
            *(float4*)(a + 4) = *(const float4*)(&As[k][ty * 8 + 4]);
            *(float4*)(b)     = *(const float4*)(&Bs[k][tx * 8]);
            *(float4*)(b + 4) = *(const float4*)(&Bs[k][tx * 8 + 4]);
#pragma unroll
            for (int i = 0; i < 8; i++)
#pragma unroll
                for (int j = 0; j < 8; j++)
                    acc[i][j] = fmaf(a[i], b[j], acc[i][j]);
        }
        __syncthreads();
    }

#pragma unroll
    for (int i = 0; i < 8; i++) {
        int r = m0 + ty * 8 + i;
#pragma unroll
        for (int j = 0; j < 8; j += 4) {
            int c = n0 + tx * 8 + j;
            if (c < N)
                *(float4*)(C + (size_t)r * N + c) = *(const float4*)(&acc[i][j]);
        }
    }
}

// ---------------------------------------------------------------------------
// RMSNorm: one block per row. out[i] = in[i] * rsqrt(mean(in^2)+eps) * w[i]
// ---------------------------------------------------------------------------
__global__ void rmsnorm_kernel(const float* __restrict__ in,
                               const float* __restrict__ w,
                               float* __restrict__ out,
                               int W, int in_stride)
{
    const int t = blockIdx.x;
    const float* row = in + (size_t)t * in_stride;
    float* orow = out + (size_t)t * W;

    float ss = 0.f;
    for (int i = threadIdx.x; i < W; i += blockDim.x) {
        float v = row[i];
        ss += v * v;
    }
    __shared__ float red[32];
#pragma unroll
    for (int o = 16; o; o >>= 1) ss += __shfl_xor_sync(0xffffffffu, ss, o);
    if ((threadIdx.x & 31) == 0) red[threadIdx.x >> 5] = ss;
    __syncthreads();
    if (threadIdx.x < 32) {
        float v = (threadIdx.x < (blockDim.x >> 5)) ? red[threadIdx.x] : 0.f;
#pragma unroll
        for (int o = 16; o; o >>= 1) v += __shfl_xor_sync(0xffffffffu, v, o);
        if (threadIdx.x == 0) red[0] = v;
    }
    __syncthreads();
    const float inv = rsqrtf(red[0] / (float)W + 1e-6f);
    for (int i = threadIdx.x; i < W; i += blockDim.x)
        orow[i] = row[i] * inv * w[i];
}

// ---------------------------------------------------------------------------
// RoPE (q_pe in place, k_pe from latent -> g_kpe) + llama4 scaling of q.
// One block per token.
// ---------------------------------------------------------------------------
__global__ void rope_scale_kernel(const int* __restrict__ positions,
                                  const float* __restrict__ cs_cache, // [T,64]
                                  const float* __restrict__ scaling,  // [T]
                                  const float* __restrict__ latent,   // [T,576]
                                  float* __restrict__ q,              // [T,16*192]
                                  float* __restrict__ kpe)            // [T,64]
{
    const int t = blockIdx.x;
    const int pos = positions[t];
    const float* cs = cs_cache + (size_t)pos * DR;
    const float sc = scaling[t];
    float* qrow = q + (size_t)t * (NH * DQK);

    // q_pe rope: 16 heads * 32 pairs
    for (int idx = threadIdx.x; idx < NH * 32; idx += blockDim.x) {
        int h = idx >> 5, i = idx & 31;
        float c = cs[i], s = cs[32 + i];
        float x1 = qrow[h * DQK + DN + i];
        float x2 = qrow[h * DQK + DN + 32 + i];
        qrow[h * DQK + DN + i]      = x1 * c - x2 * s;
        qrow[h * DQK + DN + 32 + i] = x2 * c + x1 * s;
    }
    // k_pe rope
    if (threadIdx.x < 32) {
        int i = threadIdx.x;
        float c = cs[i], s = cs[32 + i];
        float x1 = latent[(size_t)t * KV_A_OUT + KV_RANK + i];
        float x2 = latent[(size_t)t * KV_A_OUT + KV_RANK + 32 + i];
        kpe[t * DR + i]      = x1 * c - x2 * s;
        kpe[t * DR + 32 + i] = x2 * c + x1 * s;
    }
    __syncthreads();
    // scale full q row
    for (int i = threadIdx.x; i < NH * DQK; i += blockDim.x)
        qrow[i] *= sc;
}

// ---------------------------------------------------------------------------
// Flash attention (fp32, causal). BM=BN=64, 256 threads.
//   q:   [T, 16, 192]
//   kv:  [T, 16, 256]  (k_nope = [:,:,0:128], v = [:,:,128:256])
//   kpe: [T, 64]       (shared across heads)
//   out: [T, 16*128]
// ---------------------------------------------------------------------------
#define FBM 64
#define FBN 64
#define QK_PAD 193                // padded stride for Qs/Ks (bank conflicts)
#define FLASH_SMEM_FLOATS (FBM*QK_PAD + FBN*QK_PAD + FBN*DV + FBM*FBN + 3*FBM)

__global__ __launch_bounds__(256) void flash_kernel(
    const float* __restrict__ q,
    const float* __restrict__ kv,
    const float* __restrict__ kpe,
    float* __restrict__ attn)
{
    extern __shared__ float fsm[];
    float* Qs   = fsm;                       // [64][193]
    float* Ks   = Qs + FBM * QK_PAD;         // [64][193]
    float* Vs   = Ks + FBN * QK_PAD;         // [64][128]
    float* Ss   = Vs + FBN * DV;             // [64][64]
    float* rowm = Ss + FBM * FBN;            // [64]
    float* rowl = rowm + FBM;                // [64]
    float* rowf = rowl + FBM;                // [64]

    const int m0  = blockIdx.x * FBM;
    const int h   = blockIdx.y;
    const int tid = threadIdx.x;
    const int ty  = tid >> 4;     // 0..15  -> S rows ty*4..+4
    const int tx  = tid & 15;     // 0..15  -> S cols tx*4..+4, O cols tx*8..+8
    const int warp = tid >> 5;
    const int lane = tid & 31;

    // Load Q tile (scalar smem stores due to odd pad)
    for (int i = tid; i < FBM * (DQK / 4); i += 256) {
        int r = i / 48, c4 = (i % 48) * 4;
        float4 v = *(const float4*)(q + (size_t)(m0 + r) * (NH * DQK) + h * DQK + c4);
        float* dst = &Qs[r * QK_PAD + c4];
        dst[0] = v.x; dst[1] = v.y; dst[2] = v.z; dst[3] = v.w;
    }
    if (tid < FBM) { rowm[tid] = -1e30f; rowl[tid] = 0.f; }

    float o[4][8];
#pragma unroll
    for (int i = 0; i < 4; i++)
#pragma unroll
        for (int j = 0; j < 8; j++) o[i][j] = 0.f;

    const float scale = 0.07216878364870322f;  // 1/sqrt(192)
    const int ntiles = m0 / FBN + 1;

    for (int nt = 0; nt < ntiles; nt++) {
        const int n0 = nt * FBN;
        __syncthreads();   // protect Ks/Vs/Ss reuse (and Qs on first iter)

        // K nope: 64 x 128
        for (int i = tid; i < FBN * 32; i += 256) {
            int r = i >> 5, c4 = (i & 31) * 4;
            float4 v = *(const float4*)(kv + (size_t)(n0 + r) * (NH * 256) + h * 256 + c4);
            float* dst = &Ks[r * QK_PAD + c4];
            dst[0] = v.x; dst[1] = v.y; dst[2] = v.z; dst[3] = v.w;
        }
        // K pe: 64 x 64
        for (int i = tid; i < FBN * 16; i += 256) {
            int r = i >> 4, c4 = (i & 15) * 4;
            float4 v = *(const float4*)(kpe + (size_t)(n0 + r) * DR + c4);
            float* dst = &Ks[r * QK_PAD + DN + c4];
            dst[0] = v.x; dst[1] = v.y; dst[2] = v.z; dst[3] = v.w;
        }
        // V: 64 x 128
        for (int i = tid; i < FBN * 32; i += 256) {
            int r = i >> 5, c4 = (i & 31) * 4;
            *(float4*)(&Vs[r * DV + c4]) =
                *(const float4*)(kv + (size_t)(n0 + r) * (NH * 256) + h * 256 + DN + c4);
        }
        __syncthreads();

        // S = scale * Q K^T (4x4 per thread)
        float s[4][4];
#pragma unroll
        for (int i = 0; i < 4; i++)
#pragma unroll
            for (int j = 0; j < 4; j++) s[i][j] = 0.f;

#pragma unroll 4
        for (int k = 0; k < DQK; k++) {
            float qa[4], kb[4];
#pragma unroll
            for (int i = 0; i < 4; i++) qa[i] = Qs[(ty * 4 + i) * QK_PAD + k];
#pragma unroll
            for (int j = 0; j < 4; j++) kb[j] = Ks[(tx * 4 + j) * QK_PAD + k];
#pragma unroll
            for (int i = 0; i < 4; i++)
#pragma unroll
                for (int j = 0; j < 4; j++)
                    s[i][j] = fmaf(qa[i], kb[j], s[i][j]);
        }
#pragma unroll
        for (int i = 0; i < 4; i++)
#pragma unroll
            for (int j = 0; j < 4; j++) s[i][j] *= scale;

        if (nt == ntiles - 1) {  // causal mask only on diagonal tile
#pragma unroll
            for (int i = 0; i < 4; i++)
#pragma unroll
                for (int j = 0; j < 4; j++)
                    if (n0 + tx * 4 + j > m0 + ty * 4 + i) s[i][j] = -1e30f;
        }
#pragma unroll
        for (int i = 0; i < 4; i++)
            *(float4*)(&Ss[(ty * 4 + i) * FBN + tx * 4]) = *(const float4*)(&s[i][0]);
        __syncthreads();

        // Online softmax: one warp per row, rows r = warp, warp+8, ...
        for (int r = warp; r < FBM; r += 8) {
            float v0 = Ss[r * FBN + lane];
            float v1 = Ss[r * FBN + lane + 32];
            float mx = fmaxf(v0, v1);
#pragma unroll
            for (int o2 = 16; o2; o2 >>= 1) mx = fmaxf(mx, __shfl_xor_sync(0xffffffffu, mx, o2));
            float m_new = fmaxf(rowm[r], mx);
            float p0 = __expf(v0 - m_new);
            float p1 = __expf(v1 - m_new);
            float sum = p0 + p1;
#pragma unroll
            for (int o2 = 16; o2; o2 >>= 1) sum += __shfl_xor_sync(0xffffffffu, sum, o2);
            Ss[r * FBN + lane]      = p0;
            Ss[r * FBN + lane + 32] = p1;
            if (lane == 0) {
                float f = __expf(rowm[r] - m_new);
                rowf[r] = f;
                rowl[r] = rowl[r] * f + sum;
                rowm[r] = m_new;
            }
        }
        __syncthreads();

        // O = O*f + P @ V
        float f[4];
#pragma unroll
        for (int i = 0; i < 4; i++) f[i] = rowf[ty * 4 + i];
#pragma unroll
        for (int i = 0; i < 4; i++)
#pragma unroll
            for (int j = 0; j < 8; j++) o[i][j] *= f[i];

#pragma unroll 4
        for (int kk = 0; kk < FBN; kk++) {
            float p[4];
#pragma unroll
            for (int i = 0; i < 4; i++) p[i] = Ss[(ty * 4 + i) * FBN + kk];
            float vv[8];
            *(float4*)(vv)     = *(const float4*)(&Vs[kk * DV + tx * 8]);
            *(float4*)(vv + 4) = *(const float4*)(&Vs[kk * DV + tx * 8 + 4]);
#pragma unroll
            for (int i = 0; i < 4; i++)
#pragma unroll
                for (int j = 0; j < 8; j++)
                    o[i][j] = fmaf(p[i], vv[j], o[i][j]);
        }
    }

    // Final normalize + store: attn[(m0+row)*2048 + h*128 + col]
#pragma unroll
    for (int i = 0; i < 4; i++) {
        float il = 1.f / rowl[ty * 4 + i];
        float res[8];
#pragma unroll
        for (int j = 0; j < 8; j++) res[j] = o[i][j] * il;
        float* dst = attn + (size_t)(m0 + ty * 4 + i) * (NH * DV) + h * DV + tx * 8;
        *(float4*)(dst)     = *(const float4*)(&res[0]);
        *(float4*)(dst + 4) = *(const float4*)(&res[4]);
    }
}

// ---------------------------------------------------------------------------
// Launch
// ---------------------------------------------------------------------------
extern "C" void kernel_launch(void* const* d_in, const int* in_sizes, int n_in,
                              void* d_out, int out_size)
{
    const int*   positions = (const int*)  d_in[0];
    const float* hidden    = (const float*)d_in[1];
    const float* scaling   = (const float*)d_in[2];
    const float* w_q_a     = (const float*)d_in[3];
    const float* q_a_ln_w  = (const float*)d_in[4];
    const float* w_q_b     = (const float*)d_in[5];
    const float* w_kv_a    = (const float*)d_in[6];
    const float* kv_a_ln_w = (const float*)d_in[7];
    const float* w_kv_b    = (const float*)d_in[8];
    const float* w_o       = (const float*)d_in[9];
    const float* cs_cache  = (const float*)d_in[10];
    float* out = (float*)d_out;

    float *qa, *latent, *kvan, *qb, *kv, *kpe, *attn;
    cudaGetSymbolAddress((void**)&qa,     g_qa);
    cudaGetSymbolAddress((void**)&latent, g_latent);
    cudaGetSymbolAddress((void**)&kvan,   g_kvan);
    cudaGetSymbolAddress((void**)&qb,     g_q);
    cudaGetSymbolAddress((void**)&kv,     g_kv);
    cudaGetSymbolAddress((void**)&kpe,    g_kpe);
    cudaGetSymbolAddress((void**)&attn,   g_attn);

    const dim3 blk(256);
    const int MT = T_TOK / BM;  // 24 row tiles

    // q_a = hidden @ w_q_a              [3072,5120]x[5120,1536]
    sgemm_kernel<<<dim3(Q_RANK / BN, MT), blk>>>(hidden, w_q_a, qa, T_TOK, Q_RANK, HID);
    // latent = hidden @ w_kv_a          [3072,5120]x[5120,576]
    sgemm_kernel<<<dim3((KV_A_OUT + BN - 1) / BN, MT), blk>>>(hidden, w_kv_a, latent, T_TOK, KV_A_OUT, HID);
    // rmsnorm
    rmsnorm_kernel<<<T_TOK, 256>>>(qa, q_a_ln_w, qa, Q_RANK, Q_RANK);
    rmsnorm_kernel<<<T_TOK, 256>>>(latent, kv_a_ln_w, kvan, KV_RANK, KV_A_OUT);
    // q = q_a_norm @ w_q_b              [3072,1536]x[1536,3072]
    sgemm_kernel<<<dim3((NH * DQK) / BN, MT), blk>>>(qa, w_q_b, qb, T_TOK, NH * DQK, Q_RANK);
    // kv = kv_a_norm @ w_kv_b           [3072,512]x[512,4096]
    sgemm_kernel<<<dim3((NH * 256) / BN, MT), blk>>>(kvan, w_kv_b, kv, T_TOK, NH * 256, KV_RANK);
    // rope + scaling
    rope_scale_kernel<<<T_TOK, 256>>>(positions, cs_cache, scaling, latent, qb, kpe);
    // flash attention
    static int smem_set = 0;
    const int flash_smem = FLASH_SMEM_FLOATS * (int)sizeof(float);
    if (!smem_set) {
        cudaFuncSetAttribute(flash_kernel, cudaFuncAttributeMaxDynamicSharedMemorySize, flash_smem);
        smem_set = 1;
    }
    flash_kernel<<<dim3(T_TOK / FBM, NH), 256, flash_smem>>>(qb, kv, kpe, attn);
    // out = attn @ w_o                  [3072,2048]x[2048,5120]
    sgemm_kernel<<<dim3(HID / BN, MT), blk>>>(attn, w_o, out, T_TOK, HID, NH * DV);
}

// round 2
// speedup vs baseline: 1.7316x; 1.7316x over previous
#include <cuda_runtime.h>
#include <cuda_bf16.h>
#include <math.h>

// Problem constants
#define T_TOK 3072
#define HID 5120
#define NH 16
#define DN 128
#define DR 64
#define DQK 192       // DN + DR
#define DV 128
#define Q_RANK 1536
#define KV_RANK 512
#define KV_A_OUT (KV_RANK + DR)   // 576
#define KV_OUT (DN + DV)          // 256

typedef __nv_bfloat16 bf16;

// ---------------------------------------------------------------------------
// Scratch (allocation-free: __device__ globals)
// ---------------------------------------------------------------------------
// split inputs/weights (hi/lo bf16)
__device__ bf16 g_Hh[T_TOK * HID],        g_Hl[T_TOK * HID];
__device__ bf16 g_Wqa_h[HID * Q_RANK],    g_Wqa_l[HID * Q_RANK];
__device__ bf16 g_Wkva_h[HID * KV_A_OUT], g_Wkva_l[HID * KV_A_OUT];
__device__ bf16 g_Wqb_h[Q_RANK * NH * DQK],  g_Wqb_l[Q_RANK * NH * DQK];
__device__ bf16 g_Wkvb_h[KV_RANK * NH * KV_OUT], g_Wkvb_l[KV_RANK * NH * KV_OUT];
__device__ bf16 g_Wo_h[NH * DV * HID],    g_Wo_l[NH * DV * HID];
// activations
__device__ float g_qa[T_TOK * Q_RANK];        // q_a pre-norm (fp32)
__device__ bf16  g_qa_h[T_TOK * Q_RANK], g_qa_l[T_TOK * Q_RANK];
__device__ float g_latent[T_TOK * KV_A_OUT];
__device__ bf16  g_kvan_h[T_TOK * KV_RANK], g_kvan_l[T_TOK * KV_RANK];
__device__ float g_q[T_TOK * NH * DQK];       // q (rope + scale in place)
__device__ float g_kv[T_TOK * NH * KV_OUT];
__device__ float g_kpe[T_TOK * DR];
__device__ bf16  g_attn_h[T_TOK * NH * DV], g_attn_l[T_TOK * NH * DV];

// ---------------------------------------------------------------------------
// PTX helpers
// ---------------------------------------------------------------------------
__device__ __forceinline__ unsigned smem_u32(const void* p) {
    return (unsigned)__cvta_generic_to_shared(p);
}
__device__ __forceinline__ void cp16(unsigned s, const void* g, int srcsz) {
    asm volatile("cp.async.cg.shared.global [%0], [%1], 16, %2;\n"
                 :: "r"(s), "l"(g), "r"(srcsz));
}
__device__ __forceinline__ void cp_commit() {
    asm volatile("cp.async.commit_group;\n" ::);
}
template<int N> __device__ __forceinline__ void cp_wait() {
    asm volatile("cp.async.wait_group %0;\n" :: "n"(N));
}
__device__ __forceinline__ void ldm4(unsigned* d, unsigned a) {
    asm volatile("ldmatrix.sync.aligned.m8n8.x4.shared.b16 {%0,%1,%2,%3}, [%4];\n"
                 : "=r"(d[0]), "=r"(d[1]), "=r"(d[2]), "=r"(d[3]) : "r"(a));
}
__device__ __forceinline__ void ldm4t(unsigned* d, unsigned a) {
    asm volatile("ldmatrix.sync.aligned.m8n8.x4.trans.shared.b16 {%0,%1,%2,%3}, [%4];\n"
                 : "=r"(d[0]), "=r"(d[1]), "=r"(d[2]), "=r"(d[3]) : "r"(a));
}
__device__ __forceinline__ void mma16816(float* c, const unsigned* a, const unsigned* b) {
    asm volatile(
        "mma.sync.aligned.m16n8k16.row.col.f32.bf16.bf16.f32 "
        "{%0,%1,%2,%3}, {%4,%5,%6,%7}, {%8,%9}, {%0,%1,%2,%3};\n"
        : "+f"(c[0]), "+f"(c[1]), "+f"(c[2]), "+f"(c[3])
        : "r"(a[0]), "r"(a[1]), "r"(a[2]), "r"(a[3]), "r"(b[0]), "r"(b[1]));
}
__device__ __forceinline__ void split1(float x, bf16& h, bf16& l) {
    h = __float2bfloat16_rn(x);
    l = __float2bfloat16_rn(x - __bfloat162float(h));
}

// ---------------------------------------------------------------------------
// Split-convert: fp32 -> (hi, lo) bf16. n must be a multiple of 4.
// ---------------------------------------------------------------------------
__global__ void split_kernel(const float* __restrict__ x,
                             bf16* __restrict__ hi, bf16* __restrict__ lo, int n4)
{
    int i = blockIdx.x * blockDim.x + threadIdx.x;
    if (i >= n4) return;
    float4 v = ((const float4*)x)[i];
    bf16 h0, h1, h2, h3, l0, l1, l2, l3;
    split1(v.x, h0, l0); split1(v.y, h1, l1); split1(v.z, h2, l2); split1(v.w, h3, l3);
    __nv_bfloat162* H = (__nv_bfloat162*)hi;
    __nv_bfloat162* L = (__nv_bfloat162*)lo;
    H[i * 2]     = __nv_bfloat162(h0, h1);
    H[i * 2 + 1] = __nv_bfloat162(h2, h3);
    L[i * 2]     = __nv_bfloat162(l0, l1);
    L[i * 2 + 1] = __nv_bfloat162(l2, l3);
}

// ---------------------------------------------------------------------------
// Split-bf16 tensor-core GEMM:  C[M,N] = A[M,K] @ B[K,N]  (fp32 math via
// 3-term bf16 split: Ah*Bh + Ah*Bl + Al*Bh, fp32 accumulate).
// CTA 128x128, BK=32, 256 threads (8 warps, warp tile 64x32), cp.async
// double buffer, XOR-swizzled smem + ldmatrix.
// Requires: M%128==0, K%32==0, N%8==0 (N<tile handled by masking).
// ---------------------------------------------------------------------------
#define CBM 128
#define CBN 128
#define CBK 32
#define A_TILE_B 8192      // 128*32*2
#define B_TILE_B 8192      // 32*128*2
#define STAGE_B  (2 * A_TILE_B + 2 * B_TILE_B)   // Ah, Al, Bh, Bl

__global__ __launch_bounds__(256) void mma_gemm_kernel(
    const bf16* __restrict__ Ah, const bf16* __restrict__ Al,
    const bf16* __restrict__ Bh, const bf16* __restrict__ Bl,
    float* __restrict__ C, int M, int N, int K)
{
    extern __shared__ char smem[];
    const int tid  = threadIdx.x;
    const int lane = tid & 31;
    const int warp = tid >> 5;
    const int wm0 = (warp >> 2) * 64;   // 0 / 64
    const int wn0 = (warp & 3) * 32;    // 0..96
    const int m0 = blockIdx.y * CBM;
    const int n0 = blockIdx.x * CBN;

    float acc[16][4];
#pragma unroll
    for (int i = 0; i < 16; i++)
#pragma unroll
        for (int j = 0; j < 4; j++) acc[i][j] = 0.f;

    // ---- stage loader ----
    auto load_stage = [&](int k0, int s) {
        char* base = smem + s * STAGE_B;
#pragma unroll
        for (int i = 0; i < 2; i++) {           // A: 512 chunks of 16B per tile
            int ch = tid + i * 256;
            int r = ch >> 2, c = ch & 3;
            int pc = c ^ ((r >> 1) & 3);
            size_t goff = (size_t)(m0 + r) * K + k0 + c * 8;
            cp16(smem_u32(base + r * 64 + pc * 16), Ah + goff, 16);
            cp16(smem_u32(base + A_TILE_B + r * 64 + pc * 16), Al + goff, 16);
        }
#pragma unroll
        for (int i = 0; i < 2; i++) {           // B: 512 chunks of 16B per tile
            int ch = tid + i * 256;
            int r = ch >> 4, c = ch & 15;
            int pc = c ^ (r & 7);
            int gn = n0 + c * 8;
            int sz = (gn < N) ? 16 : 0;
            size_t goff = (size_t)(k0 + r) * N + (gn < N ? gn : 0);
            cp16(smem_u32(base + 2 * A_TILE_B + r * 256 + pc * 16), Bh + goff, sz);
            cp16(smem_u32(base + 2 * A_TILE_B + B_TILE_B + r * 256 + pc * 16), Bl + goff, sz);
        }
    };

    // ---- compute one stage ----
    auto compute_stage = [&](int s) {
        char* base = smem + s * STAGE_B;
        unsigned aH = smem_u32(base);
        unsigned aL = aH + A_TILE_B;
        unsigned bH = aH + 2 * A_TILE_B;
        unsigned bL = bH + B_TILE_B;
#pragma unroll
        for (int kk = 0; kk < 2; kk++) {
            unsigned ah[4][4], al[4][4], bh[4][2], bl[4][2];
            const int r_lo = lane & 15;
            const int cch = kk * 2 + (lane >> 4);
#pragma unroll
            for (int mi = 0; mi < 4; mi++) {
                int r = wm0 + mi * 16 + r_lo;
                int pc = cch ^ ((r >> 1) & 3);
                unsigned off = (unsigned)(r * 64 + pc * 16);
                ldm4(ah[mi], aH + off);
                ldm4(al[mi], aL + off);
            }
            {
                int r = kk * 16 + (lane & 15);
#pragma unroll
                for (int ni = 0; ni < 2; ni++) {
                    int cc = ((wn0 + ni * 16) >> 3) + ((lane >> 4) & 1);
                    int pc = cc ^ (r & 7);
                    unsigned off = (unsigned)(r * 256 + pc * 16);
                    unsigned t[4];
                    ldm4t(t, bH + off);
                    bh[ni * 2][0] = t[0]; bh[ni * 2][1] = t[1];
                    bh[ni * 2 + 1][0] = t[2]; bh[ni * 2 + 1][1] = t[3];
                    ldm4t(t, bL + off);
                    bl[ni * 2][0] = t[0]; bl[ni * 2][1] = t[1];
                    bl[ni * 2 + 1][0] = t[2]; bl[ni * 2 + 1][1] = t[3];
                }
            }
#pragma unroll
            for (int mi = 0; mi < 4; mi++)
#pragma unroll
                for (int nj = 0; nj < 4; nj++) {
                    mma16816(acc[mi * 4 + nj], ah[mi], bh[nj]);
                    mma16816(acc[mi * 4 + nj], ah[mi], bl[nj]);
                    mma16816(acc[mi * 4 + nj], al[mi], bh[nj]);
                }
        }
    };

    const int KT = K / CBK;
    load_stage(0, 0);
    cp_commit();
    for (int kt = 0; kt < KT; kt++) {
        if (kt + 1 < KT) load_stage((kt + 1) * CBK, (kt + 1) & 1);
        cp_commit();
        cp_wait<1>();
        __syncthreads();
        compute_stage(kt & 1);
        __syncthreads();
    }

    // ---- epilogue ----
#pragma unroll
    for (int mi = 0; mi < 4; mi++) {
        int row = m0 + wm0 + mi * 16 + (lane >> 2);
#pragma unroll
        for (int nj = 0; nj < 4; nj++) {
            int col = n0 + wn0 + nj * 8 + (lane & 3) * 2;
            if (col < N) {
                float* a = acc[mi * 4 + nj];
                *(float2*)(C + (size_t)row * N + col)       = make_float2(a[0], a[1]);
                *(float2*)(C + (size_t)(row + 8) * N + col) = make_float2(a[2], a[3]);
            }
        }
    }
}

// ---------------------------------------------------------------------------
// RMSNorm + split: out_hi/lo[i] = split(in[i] * rsqrt(mean(in^2)+eps) * w[i])
// ---------------------------------------------------------------------------
__global__ void rmsnorm_split_kernel(const float* __restrict__ in,
                                     const float* __restrict__ w,
                                     bf16* __restrict__ ohi, bf16* __restrict__ olo,
                                     int W, int in_stride)
{
    const int t = blockIdx.x;
    const float* row = in + (size_t)t * in_stride;

    float ss = 0.f;
    for (int i = threadIdx.x; i < W; i += blockDim.x) {
        float v = row[i];
        ss += v * v;
    }
    __shared__ float red[32];
#pragma unroll
    for (int o = 16; o; o >>= 1) ss += __shfl_xor_sync(0xffffffffu, ss, o);
    if ((threadIdx.x & 31) == 0) red[threadIdx.x >> 5] = ss;
    __syncthreads();
    if (threadIdx.x < 32) {
        float v = (threadIdx.x < (blockDim.x >> 5)) ? red[threadIdx.x] : 0.f;
#pragma unroll
        for (int o = 16; o; o >>= 1) v += __shfl_xor_sync(0xffffffffu, v, o);
        if (threadIdx.x == 0) red[0] = v;
    }
    __syncthreads();
    const float inv = rsqrtf(red[0] / (float)W + 1e-6f);
    for (int i = threadIdx.x; i < W; i += blockDim.x) {
        float y = row[i] * inv * w[i];
        bf16 h, l;
        split1(y, h, l);
        ohi[(size_t)t * W + i] = h;
        olo[(size_t)t * W + i] = l;
    }
}

// ---------------------------------------------------------------------------
// RoPE (q_pe in place, k_pe from latent -> g_kpe) + llama4 scaling of q.
// ---------------------------------------------------------------------------
__global__ void rope_scale_kernel(const int* __restrict__ positions,
                                  const float* __restrict__ cs_cache, // [T,64]
                                  const float* __restrict__ scaling,  // [T]
                                  const float* __restrict__ latent,   // [T,576]
                                  float* __restrict__ q,              // [T,16*192]
                                  float* __restrict__ kpe)            // [T,64]
{
    const int t = blockIdx.x;
    const int pos = positions[t];
    const float* cs = cs_cache + (size_t)pos * DR;
    const float sc = scaling[t];
    float* qrow = q + (size_t)t * (NH * DQK);

    for (int idx = threadIdx.x; idx < NH * 32; idx += blockDim.x) {
        int h = idx >> 5, i = idx & 31;
        float c = cs[i], s = cs[32 + i];
        float x1 = qrow[h * DQK + DN + i];
        float x2 = qrow[h * DQK + DN + 32 + i];
        qrow[h * DQK + DN + i]      = x1 * c - x2 * s;
        qrow[h * DQK + DN + 32 + i] = x2 * c + x1 * s;
    }
    if (threadIdx.x < 32) {
        int i = threadIdx.x;
        float c = cs[i], s = cs[32 + i];
        float x1 = latent[(size_t)t * KV_A_OUT + KV_RANK + i];
        float x2 = latent[(size_t)t * KV_A_OUT + KV_RANK + 32 + i];
        kpe[t * DR + i]      = x1 * c - x2 * s;
        kpe[t * DR + 32 + i] = x2 * c + x1 * s;
    }
    __syncthreads();
    for (int i = threadIdx.x; i < NH * DQK; i += blockDim.x)
        qrow[i] *= sc;
}

// ---------------------------------------------------------------------------
// Flash attention (fp32, causal). BM=BN=64, 256 threads.
// Epilogue writes split bf16 (hi/lo) for the w_o GEMM.
// ---------------------------------------------------------------------------
#define FBM 64
#define FBN 64
#define QK_PAD 193
#define FLASH_SMEM_FLOATS (FBM*QK_PAD + FBN*QK_PAD + FBN*DV + FBM*FBN + 3*FBM)

__global__ __launch_bounds__(256) void flash_kernel(
    const float* __restrict__ q,
    const float* __restrict__ kv,
    const float* __restrict__ kpe,
    bf16* __restrict__ attn_h,
    bf16* __restrict__ attn_l)
{
    extern __shared__ float fsm[];
    float* Qs   = fsm;
    float* Ks   = Qs + FBM * QK_PAD;
    float* Vs   = Ks + FBN * QK_PAD;
    float* Ss   = Vs + FBN * DV;
    float* rowm = Ss + FBM * FBN;
    float* rowl = rowm + FBM;
    float* rowf = rowl + FBM;

    const int m0  = blockIdx.x * FBM;
    const int h   = blockIdx.y;
    const int tid = threadIdx.x;
    const int ty  = tid >> 4;
    const int tx  = tid & 15;
    const int warp = tid >> 5;
    const int lane = tid & 31;

    for (int i = tid; i < FBM * (DQK / 4); i += 256) {
        int r = i / 48, c4 = (i % 48) * 4;
        float4 v = *(const float4*)(q + (size_t)(m0 + r) * (NH * DQK) + h * DQK + c4);
        float* dst = &Qs[r * QK_PAD + c4];
        dst[0] = v.x; dst[1] = v.y; dst[2] = v.z; dst[3] = v.w;
    }
    if (tid < FBM) { rowm[tid] = -1e30f; rowl[tid] = 0.f; }

    float o[4][8];
#pragma unroll
    for (int i = 0; i < 4; i++)
#pragma unroll
        for (int j = 0; j < 8; j++) o[i][j] = 0.f;

    const float scale = 0.07216878364870322f;  // 1/sqrt(192)
    const int ntiles = m0 / FBN + 1;

    for (int nt = 0; nt < ntiles; nt++) {
        const int n0 = nt * FBN;
        __syncthreads();

        for (int i = tid; i < FBN * 32; i += 256) {
            int r = i >> 5, c4 = (i & 31) * 4;
            float4 v = *(const float4*)(kv + (size_t)(n0 + r) * (NH * 256) + h * 256 + c4);
            float* dst = &Ks[r * QK_PAD + c4];
            dst[0] = v.x; dst[1] = v.y; dst[2] = v.z; dst[3] = v.w;
        }
        for (int i = tid; i < FBN * 16; i += 256) {
            int r = i >> 4, c4 = (i & 15) * 4;
            float4 v = *(const float4*)(kpe + (size_t)(n0 + r) * DR + c4);
            float* dst = &Ks[r * QK_PAD + DN + c4];
            dst[0] = v.x; dst[1] = v.y; dst[2] = v.z; dst[3] = v.w;
        }
        for (int i = tid; i < FBN * 32; i += 256) {
            int r = i >> 5, c4 = (i & 31) * 4;
            *(float4*)(&Vs[r * DV + c4]) =
                *(const float4*)(kv + (size_t)(n0 + r) * (NH * 256) + h * 256 + DN + c4);
        }
        __syncthreads();

        float s[4][4];
#pragma unroll
        for (int i = 0; i < 4; i++)
#pragma unroll
            for (int j = 0; j < 4; j++) s[i][j] = 0.f;

#pragma unroll 4
        for (int k = 0; k < DQK; k++) {
            float qa[4], kb[4];
#pragma unroll
            for (int i = 0; i < 4; i++) qa[i] = Qs[(ty * 4 + i) * QK_PAD + k];
#pragma unroll
            for (int j = 0; j < 4; j++) kb[j] = Ks[(tx * 4 + j) * QK_PAD + k];
#pragma unroll
            for (int i = 0; i < 4; i++)
#pragma unroll
                for (int j = 0; j < 4; j++)
                    s[i][j] = fmaf(qa[i], kb[j], s[i][j]);
        }
#pragma unroll
        for (int i = 0; i < 4; i++)
#pragma unroll
            for (int j = 0; j < 4; j++) s[i][j] *= scale;

        if (nt == ntiles - 1) {
#pragma unroll
            for (int i = 0; i < 4; i++)
#pragma unroll
                for (int j = 0; j < 4; j++)
                    if (n0 + tx * 4 + j > m0 + ty * 4 + i) s[i][j] = -1e30f;
        }
#pragma unroll
        for (int i = 0; i < 4; i++)
            *(float4*)(&Ss[(ty * 4 + i) * FBN + tx * 4]) = *(const float4*)(&s[i][0]);
        __syncthreads();

        for (int r = warp; r < FBM; r += 8) {
            float v0 = Ss[r * FBN + lane];
            float v1 = Ss[r * FBN + lane + 32];
            float mx = fmaxf(v0, v1);
#pragma unroll
            for (int o2 = 16; o2; o2 >>= 1) mx = fmaxf(mx, __shfl_xor_sync(0xffffffffu, mx, o2));
            float m_new = fmaxf(rowm[r], mx);
            float p0 = __expf(v0 - m_new);
            float p1 = __expf(v1 - m_new);
            float sum = p0 + p1;
#pragma unroll
            for (int o2 = 16; o2; o2 >>= 1) sum += __shfl_xor_sync(0xffffffffu, sum, o2);
            Ss[r * FBN + lane]      = p0;
            Ss[r * FBN + lane + 32] = p1;
            if (lane == 0) {
                float f = __expf(rowm[r] - m_new);
                rowf[r] = f;
                rowl[r] = rowl[r] * f + sum;
                rowm[r] = m_new;
            }
        }
        __syncthreads();

        float f[4];
#pragma unroll
        for (int i = 0; i < 4; i++) f[i] = rowf[ty * 4 + i];
#pragma unroll
        for (int i = 0; i < 4; i++)
#pragma unroll
            for (int j = 0; j < 8; j++) o[i][j] *= f[i];

#pragma unroll 4
        for (int kk = 0; kk < FBN; kk++) {
            float p[4];
#pragma unroll
            for (int i = 0; i < 4; i++) p[i] = Ss[(ty * 4 + i) * FBN + kk];
            float vv[8];
            *(float4*)(vv)     = *(const float4*)(&Vs[kk * DV + tx * 8]);
            *(float4*)(vv + 4) = *(const float4*)(&Vs[kk * DV + tx * 8 + 4]);
#pragma unroll
            for (int i = 0; i < 4; i++)
#pragma unroll
                for (int j = 0; j < 8; j++)
                    o[i][j] = fmaf(p[i], vv[j], o[i][j]);
        }
    }

    // Final normalize + split-store (bf16 hi/lo)
#pragma unroll
    for (int i = 0; i < 4; i++) {
        float il = 1.f / rowl[ty * 4 + i];
        size_t base = (size_t)(m0 + ty * 4 + i) * (NH * DV) + h * DV + tx * 8;
        __nv_bfloat162 hv[4], lv[4];
#pragma unroll
        for (int j = 0; j < 4; j++) {
            float v0 = o[i][2 * j] * il, v1 = o[i][2 * j + 1] * il;
            bf16 h0, l0, h1, l1;
            split1(v0, h0, l0); split1(v1, h1, l1);
            hv[j] = __nv_bfloat162(h0, h1);
            lv[j] = __nv_bfloat162(l0, l1);
        }
        *(uint2*)(attn_h + base)     = *(uint2*)(&hv[0]);
        *(uint2*)(attn_h + base + 4) = *(uint2*)(&hv[2]);
        *(uint2*)(attn_l + base)     = *(uint2*)(&lv[0]);
        *(uint2*)(attn_l + base + 4) = *(uint2*)(&lv[2]);
    }
}

// ---------------------------------------------------------------------------
// Launch
// ---------------------------------------------------------------------------
static inline void launch_split(const float* x, bf16* hi, bf16* lo, int n) {
    int n4 = n / 4;
    split_kernel<<<(n4 + 255) / 256, 256>>>(x, hi, lo, n4);
}

extern "C" void kernel_launch(void* const* d_in, const int* in_sizes, int n_in,
                              void* d_out, int out_size)
{
    const int*   positions = (const int*)  d_in[0];
    const float* hidden    = (const float*)d_in[1];
    const float* scaling   = (const float*)d_in[2];
    const float* w_q_a     = (const float*)d_in[3];
    const float* q_a_ln_w  = (const float*)d_in[4];
    const float* w_q_b     = (const float*)d_in[5];
    const float* w_kv_a    = (const float*)d_in[6];
    const float* kv_a_ln_w = (const float*)d_in[7];
    const float* w_kv_b    = (const float*)d_in[8];
    const float* w_o       = (const float*)d_in[9];
    const float* cs_cache  = (const float*)d_in[10];
    float* out = (float*)d_out;

    bf16 *Hh, *Hl, *Wqa_h, *Wqa_l, *Wkva_h, *Wkva_l, *Wqb_h, *Wqb_l;
    bf16 *Wkvb_h, *Wkvb_l, *Wo_h, *Wo_l, *qa_h, *qa_l, *kvan_h, *kvan_l;
    bf16 *attn_h, *attn_l;
    float *qa, *latent, *qb, *kv, *kpe;
    cudaGetSymbolAddress((void**)&Hh, g_Hh);       cudaGetSymbolAddress((void**)&Hl, g_Hl);
    cudaGetSymbolAddress((void**)&Wqa_h, g_Wqa_h); cudaGetSymbolAddress((void**)&Wqa_l, g_Wqa_l);
    cudaGetSymbolAddress((void**)&Wkva_h, g_Wkva_h); cudaGetSymbolAddress((void**)&Wkva_l, g_Wkva_l);
    cudaGetSymbolAddress((void**)&Wqb_h, g_Wqb_h); cudaGetSymbolAddress((void**)&Wqb_l, g_Wqb_l);
    cudaGetSymbolAddress((void**)&Wkvb_h, g_Wkvb_h); cudaGetSymbolAddress((void**)&Wkvb_l, g_Wkvb_l);
    cudaGetSymbolAddress((void**)&Wo_h, g_Wo_h);   cudaGetSymbolAddress((void**)&Wo_l, g_Wo_l);
    cudaGetSymbolAddress((void**)&qa_h, g_qa_h);   cudaGetSymbolAddress((void**)&qa_l, g_qa_l);
    cudaGetSymbolAddress((void**)&kvan_h, g_kvan_h); cudaGetSymbolAddress((void**)&kvan_l, g_kvan_l);
    cudaGetSymbolAddress((void**)&attn_h, g_attn_h); cudaGetSymbolAddress((void**)&attn_l, g_attn_l);
    cudaGetSymbolAddress((void**)&qa, g_qa);
    cudaGetSymbolAddress((void**)&latent, g_latent);
    cudaGetSymbolAddress((void**)&qb, g_q);
    cudaGetSymbolAddress((void**)&kv, g_kv);
    cudaGetSymbolAddress((void**)&kpe, g_kpe);

    cudaFuncSetAttribute(mma_gemm_kernel, cudaFuncAttributeMaxDynamicSharedMemorySize,
                         2 * STAGE_B);
    cudaFuncSetAttribute(flash_kernel, cudaFuncAttributeMaxDynamicSharedMemorySize,
                         FLASH_SMEM_FLOATS * (int)sizeof(float));

    // 1. split inputs + weights to (hi, lo) bf16
    launch_split(hidden, Hh, Hl, T_TOK * HID);
    launch_split(w_q_a, Wqa_h, Wqa_l, HID * Q_RANK);
    launch_split(w_kv_a, Wkva_h, Wkva_l, HID * KV_A_OUT);
    launch_split(w_q_b, Wqb_h, Wqb_l, Q_RANK * NH * DQK);
    launch_split(w_kv_b, Wkvb_h, Wkvb_l, KV_RANK * NH * KV_OUT);
    launch_split(w_o, Wo_h, Wo_l, NH * DV * HID);

    const dim3 blk(256);
    const int MT = T_TOK / CBM;  // 24

    // 2. qa = hidden @ w_q_a   [3072,5120]x[5120,1536]
    mma_gemm_kernel<<<dim3(Q_RANK / CBN, MT), blk, 2 * STAGE_B>>>(
        Hh, Hl, Wqa_h, Wqa_l, qa, T_TOK, Q_RANK, HID);
    // 3. latent = hidden @ w_kv_a   [3072,5120]x[5120,576]
    mma_gemm_kernel<<<dim3((KV_A_OUT + CBN - 1) / CBN, MT), blk, 2 * STAGE_B>>>(
        Hh, Hl, Wkva_h, Wkva_l, latent, T_TOK, KV_A_OUT, HID);
    // 4. rmsnorm + split
    rmsnorm_split_kernel<<<T_TOK, 256>>>(qa, q_a_ln_w, qa_h, qa_l, Q_RANK, Q_RANK);
    rmsnorm_split_kernel<<<T_TOK, 256>>>(latent, kv_a_ln_w, kvan_h, kvan_l, KV_RANK, KV_A_OUT);
    // 5. q = qa_n @ w_q_b   [3072,1536]x[1536,3072]
    mma_gemm_kernel<<<dim3((NH * DQK) / CBN, MT), blk, 2 * STAGE_B>>>(
        qa_h, qa_l, Wqb_h, Wqb_l, qb, T_TOK, NH * DQK, Q_RANK);
    // 6. kv = kvan @ w_kv_b   [3072,512]x[512,4096]
    mma_gemm_kernel<<<dim3((NH * KV_OUT) / CBN, MT), blk, 2 * STAGE_B>>>(
        kvan_h, kvan_l, Wkvb_h, Wkvb_l, kv, T_TOK, NH * KV_OUT, KV_RANK);
    // 7. rope + scaling
    rope_scale_kernel<<<T_TOK, 256>>>(positions, cs_cache, scaling, latent, qb, kpe);
    // 8. flash attention (writes split attn)
    flash_kernel<<<dim3(T_TOK / FBM, NH), 256, FLASH_SMEM_FLOATS * (int)sizeof(float)>>>(
        qb, kv, kpe, attn_h, attn_l);
    // 9. out = attn @ w_o   [3072,2048]x[2048,5120]
    mma_gemm_kernel<<<dim3(HID / CBN, MT), blk, 2 * STAGE_B>>>(
        attn_h, attn_l, Wo_h, Wo_l, out, T_TOK, HID, NH * DV);
}

// round 3
// speedup vs baseline: 3.4868x; 2.0137x over previous
#include <cuda_runtime.h>
#include <cuda_bf16.h>
#include <math.h>

// Problem constants
#define T_TOK 3072
#define HID 5120
#define NH 16
#define DN 128
#define DR 64
#define DQK 192       // DN + DR
#define DV 128
#define Q_RANK 1536
#define KV_RANK 512
#define KV_A_OUT (KV_RANK + DR)   // 576
#define KV_OUT (DN + DV)          // 256

typedef __nv_bfloat16 bf16;

// ---------------------------------------------------------------------------
// Scratch (allocation-free: __device__ globals)
// ---------------------------------------------------------------------------
__device__ bf16 g_Hh[T_TOK * HID],        g_Hl[T_TOK * HID];
__device__ bf16 g_Wqa_h[HID * Q_RANK],    g_Wqa_l[HID * Q_RANK];
__device__ bf16 g_Wkva_h[HID * KV_A_OUT], g_Wkva_l[HID * KV_A_OUT];
__device__ bf16 g_Wqb_h[Q_RANK * NH * DQK],  g_Wqb_l[Q_RANK * NH * DQK];
__device__ bf16 g_Wkvb_h[KV_RANK * NH * KV_OUT], g_Wkvb_l[KV_RANK * NH * KV_OUT];
__device__ bf16 g_Wo_h[NH * DV * HID],    g_Wo_l[NH * DV * HID];
__device__ float g_qa[T_TOK * Q_RANK];
__device__ bf16  g_qa_h[T_TOK * Q_RANK], g_qa_l[T_TOK * Q_RANK];
__device__ float g_latent[T_TOK * KV_A_OUT];
__device__ bf16  g_kvan_h[T_TOK * KV_RANK], g_kvan_l[T_TOK * KV_RANK];
__device__ float g_q[T_TOK * NH * DQK];
__device__ float g_kv[T_TOK * NH * KV_OUT];
// head-major split tensors for flash mma
__device__ bf16 g_qh[NH * T_TOK * DQK], g_ql[NH * T_TOK * DQK];
__device__ bf16 g_kh[NH * T_TOK * DQK], g_kl[NH * T_TOK * DQK];
__device__ bf16 g_vh[NH * T_TOK * DV],  g_vl[NH * T_TOK * DV];
__device__ bf16 g_attn_h[T_TOK * NH * DV], g_attn_l[T_TOK * NH * DV];

// ---------------------------------------------------------------------------
// PTX helpers
// ---------------------------------------------------------------------------
__device__ __forceinline__ unsigned smem_u32(const void* p) {
    return (unsigned)__cvta_generic_to_shared(p);
}
__device__ __forceinline__ void cp16(unsigned s, const void* g, int srcsz) {
    asm volatile("cp.async.cg.shared.global [%0], [%1], 16, %2;\n"
                 :: "r"(s), "l"(g), "r"(srcsz));
}
__device__ __forceinline__ void cp_commit() {
    asm volatile("cp.async.commit_group;\n" ::);
}
template<int N> __device__ __forceinline__ void cp_wait() {
    asm volatile("cp.async.wait_group %0;\n" :: "n"(N));
}
__device__ __forceinline__ void ldm4(unsigned* d, unsigned a) {
    asm volatile("ldmatrix.sync.aligned.m8n8.x4.shared.b16 {%0,%1,%2,%3}, [%4];\n"
                 : "=r"(d[0]), "=r"(d[1]), "=r"(d[2]), "=r"(d[3]) : "r"(a));
}
__device__ __forceinline__ void ldm4t(unsigned* d, unsigned a) {
    asm volatile("ldmatrix.sync.aligned.m8n8.x4.trans.shared.b16 {%0,%1,%2,%3}, [%4];\n"
                 : "=r"(d[0]), "=r"(d[1]), "=r"(d[2]), "=r"(d[3]) : "r"(a));
}
__device__ __forceinline__ void mma16816(float* c, const unsigned* a, const unsigned* b) {
    asm volatile(
        "mma.sync.aligned.m16n8k16.row.col.f32.bf16.bf16.f32 "
        "{%0,%1,%2,%3}, {%4,%5,%6,%7}, {%8,%9}, {%0,%1,%2,%3};\n"
        : "+f"(c[0]), "+f"(c[1]), "+f"(c[2]), "+f"(c[3])
        : "r"(a[0]), "r"(a[1]), "r"(a[2]), "r"(a[3]), "r"(b[0]), "r"(b[1]));
}
__device__ __forceinline__ void split1(float x, bf16& h, bf16& l) {
    h = __float2bfloat16_rn(x);
    l = __float2bfloat16_rn(x - __bfloat162float(h));
}
__device__ __forceinline__ unsigned packbf(bf16 a, bf16 b) {
    __nv_bfloat162 t(a, b);
    return *(unsigned*)&t;
}

// ---------------------------------------------------------------------------
// Split-convert: fp32 -> (hi, lo) bf16. n multiple of 4.
// ---------------------------------------------------------------------------
__global__ void split_kernel(const float* __restrict__ x,
                             bf16* __restrict__ hi, bf16* __restrict__ lo, int n4)
{
    int i = blockIdx.x * blockDim.x + threadIdx.x;
    if (i >= n4) return;
    float4 v = ((const float4*)x)[i];
    bf16 h0, h1, h2, h3, l0, l1, l2, l3;
    split1(v.x, h0, l0); split1(v.y, h1, l1); split1(v.z, h2, l2); split1(v.w, h3, l3);
    __nv_bfloat162* H = (__nv_bfloat162*)hi;
    __nv_bfloat162* L = (__nv_bfloat162*)lo;
    H[i * 2]     = __nv_bfloat162(h0, h1);
    H[i * 2 + 1] = __nv_bfloat162(h2, h3);
    L[i * 2]     = __nv_bfloat162(l0, l1);
    L[i * 2 + 1] = __nv_bfloat162(l2, l3);
}

// ---------------------------------------------------------------------------
// Split-bf16 tensor-core GEMM (3-stage cp.async pipeline).
// ---------------------------------------------------------------------------
#define CBM 128
#define CBN 128
#define CBK 32
#define A_TILE_B 8192
#define B_TILE_B 8192
#define STAGE_B  (2 * A_TILE_B + 2 * B_TILE_B)
#define NSTAGE 3

__global__ __launch_bounds__(256) void mma_gemm_kernel(
    const bf16* __restrict__ Ah, const bf16* __restrict__ Al,
    const bf16* __restrict__ Bh, const bf16* __restrict__ Bl,
    float* __restrict__ C, int M, int N, int K)
{
    extern __shared__ char smem[];
    const int tid  = threadIdx.x;
    const int lane = tid & 31;
    const int warp = tid >> 5;
    const int wm0 = (warp >> 2) * 64;
    const int wn0 = (warp & 3) * 32;
    const int m0 = blockIdx.y * CBM;
    const int n0 = blockIdx.x * CBN;

    float acc[16][4];
#pragma unroll
    for (int i = 0; i < 16; i++)
#pragma unroll
        for (int j = 0; j < 4; j++) acc[i][j] = 0.f;

    auto load_stage = [&](int k0, int s) {
        char* base = smem + s * STAGE_B;
#pragma unroll
        for (int i = 0; i < 2; i++) {
            int ch = tid + i * 256;
            int r = ch >> 2, c = ch & 3;
            int pc = c ^ ((r >> 1) & 3);
            size_t goff = (size_t)(m0 + r) * K + k0 + c * 8;
            cp16(smem_u32(base + r * 64 + pc * 16), Ah + goff, 16);
            cp16(smem_u32(base + A_TILE_B + r * 64 + pc * 16), Al + goff, 16);
        }
#pragma unroll
        for (int i = 0; i < 2; i++) {
            int ch = tid + i * 256;
            int r = ch >> 4, c = ch & 15;
            int pc = c ^ (r & 7);
            int gn = n0 + c * 8;
            int sz = (gn < N) ? 16 : 0;
            size_t goff = (size_t)(k0 + r) * N + (gn < N ? gn : 0);
            cp16(smem_u32(base + 2 * A_TILE_B + r * 256 + pc * 16), Bh + goff, sz);
            cp16(smem_u32(base + 2 * A_TILE_B + B_TILE_B + r * 256 + pc * 16), Bl + goff, sz);
        }
    };

    auto compute_stage = [&](int s) {
        char* base = smem + s * STAGE_B;
        unsigned aH = smem_u32(base);
        unsigned aL = aH + A_TILE_B;
        unsigned bH = aH + 2 * A_TILE_B;
        unsigned bL = bH + B_TILE_B;
#pragma unroll
        for (int kk = 0; kk < 2; kk++) {
            unsigned ah[4][4], al[4][4], bh[4][2], bl[4][2];
            const int r_lo = lane & 15;
            const int cch = kk * 2 + (lane >> 4);
#pragma unroll
            for (int mi = 0; mi < 4; mi++) {
                int r = wm0 + mi * 16 + r_lo;
                int pc = cch ^ ((r >> 1) & 3);
                unsigned off = (unsigned)(r * 64 + pc * 16);
                ldm4(ah[mi], aH + off);
                ldm4(al[mi], aL + off);
            }
            {
                int r = kk * 16 + (lane & 15);
#pragma unroll
                for (int ni = 0; ni < 2; ni++) {
                    int cc = ((wn0 + ni * 16) >> 3) + ((lane >> 4) & 1);
                    int pc = cc ^ (r & 7);
                    unsigned off = (unsigned)(r * 256 + pc * 16);
                    unsigned t[4];
                    ldm4t(t, bH + off);
                    bh[ni * 2][0] = t[0]; bh[ni * 2][1] = t[1];
                    bh[ni * 2 + 1][0] = t[2]; bh[ni * 2 + 1][1] = t[3];
                    ldm4t(t, bL + off);
                    bl[ni * 2][0] = t[0]; bl[ni * 2][1] = t[1];
                    bl[ni * 2 + 1][0] = t[2]; bl[ni * 2 + 1][1] = t[3];
                }
            }
#pragma unroll
            for (int mi = 0; mi < 4; mi++)
#pragma unroll
                for (int nj = 0; nj < 4; nj++) {
                    mma16816(acc[mi * 4 + nj], ah[mi], bh[nj]);
                    mma16816(acc[mi * 4 + nj], ah[mi], bl[nj]);
                    mma16816(acc[mi * 4 + nj], al[mi], bh[nj]);
                }
        }
    };

    const int KT = K / CBK;   // >= 16 for all our shapes
    load_stage(0, 0); cp_commit();
    load_stage(CBK, 1); cp_commit();
    for (int kt = 0; kt < KT; kt++) {
        cp_wait<1>();          // positional: all but most recent group complete
        __syncthreads();
        if (kt + 2 < KT) load_stage((kt + 2) * CBK, (kt + 2) % NSTAGE);
        cp_commit();           // exactly one group per iteration (may be empty)
        compute_stage(kt % NSTAGE);
    }

#pragma unroll
    for (int mi = 0; mi < 4; mi++) {
        int row = m0 + wm0 + mi * 16 + (lane >> 2);
#pragma unroll
        for (int nj = 0; nj < 4; nj++) {
            int col = n0 + wn0 + nj * 8 + (lane & 3) * 2;
            if (col < N) {
                float* a = acc[mi * 4 + nj];
                *(float2*)(C + (size_t)row * N + col)       = make_float2(a[0], a[1]);
                *(float2*)(C + (size_t)(row + 8) * N + col) = make_float2(a[2], a[3]);
            }
        }
    }
}

// ---------------------------------------------------------------------------
// RMSNorm + split
// ---------------------------------------------------------------------------
__global__ void rmsnorm_split_kernel(const float* __restrict__ in,
                                     const float* __restrict__ w,
                                     bf16* __restrict__ ohi, bf16* __restrict__ olo,
                                     int W, int in_stride)
{
    const int t = blockIdx.x;
    const float* row = in + (size_t)t * in_stride;

    float ss = 0.f;
    for (int i = threadIdx.x; i < W; i += blockDim.x) {
        float v = row[i];
        ss += v * v;
    }
    __shared__ float red[32];
#pragma unroll
    for (int o = 16; o; o >>= 1) ss += __shfl_xor_sync(0xffffffffu, ss, o);
    if ((threadIdx.x & 31) == 0) red[threadIdx.x >> 5] = ss;
    __syncthreads();
    if (threadIdx.x < 32) {
        float v = (threadIdx.x < (blockDim.x >> 5)) ? red[threadIdx.x] : 0.f;
#pragma unroll
        for (int o = 16; o; o >>= 1) v += __shfl_xor_sync(0xffffffffu, v, o);
        if (threadIdx.x == 0) red[0] = v;
    }
    __syncthreads();
    const float inv = rsqrtf(red[0] / (float)W + 1e-6f);
    for (int i = threadIdx.x; i < W; i += blockDim.x) {
        float y = row[i] * inv * w[i];
        bf16 h, l;
        split1(y, h, l);
        ohi[(size_t)t * W + i] = h;
        olo[(size_t)t * W + i] = l;
    }
}

// ---------------------------------------------------------------------------
// Prep: RoPE q_pe (in place) + k_pe, fold (scaling * 1/sqrt(192)) into q,
// split q/k/v into head-major (hi, lo) bf16 for flash mma.
// One block per token.
// ---------------------------------------------------------------------------
__global__ void prep_kernel(const int* __restrict__ positions,
                            const float* __restrict__ cs_cache,
                            const float* __restrict__ scaling,
                            const float* __restrict__ latent,
                            float* __restrict__ qb,          // [T,16,192] in/out
                            const float* __restrict__ kvb,   // [T,16,256]
                            bf16* __restrict__ qh, bf16* __restrict__ ql,
                            bf16* __restrict__ kh, bf16* __restrict__ kl,
                            bf16* __restrict__ vh, bf16* __restrict__ vl)
{
    __shared__ float kpe_s[DR];
    const int t = blockIdx.x;
    const int pos = positions[t];
    const float* cs = cs_cache + (size_t)pos * DR;
    const float qsc = scaling[t] * 0.07216878364870322f;  // llama4 * 1/sqrt(192)
    float* qrow = qb + (size_t)t * (NH * DQK);

    // phase A: rope
    for (int idx = threadIdx.x; idx < NH * 32; idx += blockDim.x) {
        int hh = idx >> 5, i = idx & 31;
        float c = cs[i], s = cs[32 + i];
        float x1 = qrow[hh * DQK + DN + i];
        float x2 = qrow[hh * DQK + DN + 32 + i];
        qrow[hh * DQK + DN + i]      = x1 * c - x2 * s;
        qrow[hh * DQK + DN + 32 + i] = x2 * c + x1 * s;
    }
    if (threadIdx.x < 32) {
        int i = threadIdx.x;
        float c = cs[i], s = cs[32 + i];
        float x1 = latent[(size_t)t * KV_A_OUT + KV_RANK + i];
        float x2 = latent[(size_t)t * KV_A_OUT + KV_RANK + 32 + i];
        kpe_s[i]      = x1 * c - x2 * s;
        kpe_s[32 + i] = x2 * c + x1 * s;
    }
    __syncthreads();
    // phase B: split
    for (int idx = threadIdx.x; idx < NH * DQK; idx += blockDim.x) {
        int hh = idx / DQK, d = idx % DQK;
        size_t o = ((size_t)hh * T_TOK + t) * DQK + d;
        bf16 hi, lo;
        split1(qrow[idx] * qsc, hi, lo);
        qh[o] = hi; ql[o] = lo;
        float kvv = (d < DN) ? kvb[(size_t)t * (NH * KV_OUT) + hh * KV_OUT + d]
                             : kpe_s[d - DN];
        split1(kvv, hi, lo);
        kh[o] = hi; kl[o] = lo;
    }
    for (int idx = threadIdx.x; idx < NH * DV; idx += blockDim.x) {
        int hh = idx / DV, d = idx % DV;
        size_t o = ((size_t)hh * T_TOK + t) * DV + d;
        bf16 hi, lo;
        split1(kvb[(size_t)t * (NH * KV_OUT) + hh * KV_OUT + DN + d], hi, lo);
        vh[o] = hi; vl[o] = lo;
    }
}

// ---------------------------------------------------------------------------
// Tensor-core flash attention (split-bf16, causal).
// CTA: 128 q-rows x head, 8 warps (16 rows each), key tiles of 64.
// q/k: [h][T][192] hi/lo; v: [h][T][128] hi/lo. Output: split bf16 [T, 2048].
// ---------------------------------------------------------------------------
#define AM 128
#define AN 64
#define FQH 0
#define FQL (FQH + AM*384)
#define FKH (FQL + AM*384)
#define FKL (FKH + AN*384)
#define FVH (FKL + AN*384)
#define FVL (FVH + AN*256)
#define FLASH_SMEM (FVL + AN*256)    // 180224 B

__global__ __launch_bounds__(256) void flash_mma_kernel(
    const bf16* __restrict__ qh, const bf16* __restrict__ ql,
    const bf16* __restrict__ kh, const bf16* __restrict__ kl,
    const bf16* __restrict__ vh, const bf16* __restrict__ vl,
    bf16* __restrict__ attn_h, bf16* __restrict__ attn_l)
{
    extern __shared__ char smem[];
    const int m0 = blockIdx.x * AM;
    const int h  = blockIdx.y;
    const int tid = threadIdx.x, lane = tid & 31, warp = tid >> 5;
    const int wm = warp * 16;
    const float L2E = 1.4426950408889634f;

    // Q tiles (hi/lo) -> smem, swizzled
    {
        const bf16* qh_g = qh + ((size_t)h * T_TOK + m0) * DQK;
        const bf16* ql_g = ql + ((size_t)h * T_TOK + m0) * DQK;
        for (int i = tid; i < AM * 24; i += 256) {
            int r = i / 24, c = i % 24, pc = c ^ (r & 7);
            cp16(smem_u32(smem + FQH + r * 384 + pc * 16), qh_g + (size_t)r * DQK + c * 8, 16);
            cp16(smem_u32(smem + FQL + r * 384 + pc * 16), ql_g + (size_t)r * DQK + c * 8, 16);
        }
        cp_commit();
    }

    float o[16][4];
#pragma unroll
    for (int i = 0; i < 16; i++)
#pragma unroll
        for (int j = 0; j < 4; j++) o[i][j] = 0.f;
    float m0r = -1e30f, m1r = -1e30f, l0 = 0.f, l1 = 0.f;

    const unsigned aQh = smem_u32(smem + FQH), aQl = smem_u32(smem + FQL);
    const unsigned aKh = smem_u32(smem + FKH), aKl = smem_u32(smem + FKL);
    const unsigned aVh = smem_u32(smem + FVH), aVl = smem_u32(smem + FVL);

    const int ntiles = 2 * blockIdx.x + 2;
    for (int nt = 0; nt < ntiles; nt++) {
        const int n0 = nt * AN;
        __syncthreads();   // previous tile's smem fully consumed
        {
            const bf16* kh_g = kh + ((size_t)h * T_TOK + n0) * DQK;
            const bf16* kl_g = kl + ((size_t)h * T_TOK + n0) * DQK;
            for (int i = tid; i < AN * 24; i += 256) {
                int r = i / 24, c = i % 24, pc = c ^ (r & 7);
                cp16(smem_u32(smem + FKH + r * 384 + pc * 16), kh_g + (size_t)r * DQK + c * 8, 16);
                cp16(smem_u32(smem + FKL + r * 384 + pc * 16), kl_g + (size_t)r * DQK + c * 8, 16);
            }
            const bf16* vh_g = vh + ((size_t)h * T_TOK + n0) * DV;
            const bf16* vl_g = vl + ((size_t)h * T_TOK + n0) * DV;
            for (int i = tid; i < AN * 16; i += 256) {
                int r = i >> 4, c = i & 15, pc = c ^ (r & 7);
                cp16(smem_u32(smem + FVH + r * 256 + pc * 16), vh_g + (size_t)r * DV + c * 8, 16);
                cp16(smem_u32(smem + FVL + r * 256 + pc * 16), vl_g + (size_t)r * DV + c * 8, 16);
            }
        }
        cp_commit();
        cp_wait<0>();
        __syncthreads();

        // ---- S = Q K^T (split 3-term) ----
        float s[8][4];
#pragma unroll
        for (int j = 0; j < 8; j++)
#pragma unroll
            for (int c = 0; c < 4; c++) s[j][c] = 0.f;

#pragma unroll
        for (int kt = 0; kt < 12; kt++) {
            unsigned ah[4], al[4];
            {
                int r = wm + (lane & 15), c = kt * 2 + (lane >> 4);
                int pc = c ^ (r & 7);
                unsigned off = (unsigned)(r * 384 + pc * 16);
                ldm4(ah, aQh + off);
                ldm4(al, aQl + off);
            }
#pragma unroll
            for (int kb = 0; kb < 4; kb++) {
                int r = kb * 16 + (lane & 15), c = kt * 2 + (lane >> 4);
                int pc = c ^ (r & 7);
                unsigned off = (unsigned)(r * 384 + pc * 16);
                unsigned tb[4], tl[4];
                ldm4(tb, aKh + off);
                ldm4(tl, aKl + off);
                unsigned bh0[2] = {tb[0], tb[2]}, bh1[2] = {tb[1], tb[3]};
                unsigned bl0[2] = {tl[0], tl[2]}, bl1[2] = {tl[1], tl[3]};
                mma16816(s[kb * 2], ah, bh0);
                mma16816(s[kb * 2], ah, bl0);
                mma16816(s[kb * 2], al, bh0);
                mma16816(s[kb * 2 + 1], ah, bh1);
                mma16816(s[kb * 2 + 1], ah, bl1);
                mma16816(s[kb * 2 + 1], al, bh1);
            }
        }

        // ---- causal mask (only near-diagonal tiles) ----
        if (n0 + AN > m0) {
            int q0 = m0 + wm + (lane >> 2);
#pragma unroll
            for (int j = 0; j < 8; j++) {
                int k0 = n0 + j * 8 + (lane & 3) * 2;
                if (k0     > q0)     s[j][0] = -1e30f;
                if (k0 + 1 > q0)     s[j][1] = -1e30f;
                if (k0     > q0 + 8) s[j][2] = -1e30f;
                if (k0 + 1 > q0 + 8) s[j][3] = -1e30f;
            }
        }

        // ---- online softmax ----
        float mx0 = -1e30f, mx1 = -1e30f;
#pragma unroll
        for (int j = 0; j < 8; j++) {
            mx0 = fmaxf(mx0, fmaxf(s[j][0], s[j][1]));
            mx1 = fmaxf(mx1, fmaxf(s[j][2], s[j][3]));
        }
        mx0 = fmaxf(mx0, __shfl_xor_sync(0xffffffffu, mx0, 1));
        mx0 = fmaxf(mx0, __shfl_xor_sync(0xffffffffu, mx0, 2));
        mx1 = fmaxf(mx1, __shfl_xor_sync(0xffffffffu, mx1, 1));
        mx1 = fmaxf(mx1, __shfl_xor_sync(0xffffffffu, mx1, 2));
        float mn0 = fmaxf(m0r, mx0), mn1 = fmaxf(m1r, mx1);
        float f0 = exp2f((m0r - mn0) * L2E), f1 = exp2f((m1r - mn1) * L2E);
        m0r = mn0; m1r = mn1;

        unsigned ph[8], ph2[8], pl[8], pl2[8];
        float sum0 = 0.f, sum1 = 0.f;
#pragma unroll
        for (int j = 0; j < 8; j++) {
            float p0 = exp2f((s[j][0] - mn0) * L2E);
            float p1 = exp2f((s[j][1] - mn0) * L2E);
            float p2 = exp2f((s[j][2] - mn1) * L2E);
            float p3 = exp2f((s[j][3] - mn1) * L2E);
            sum0 += p0 + p1; sum1 += p2 + p3;
            bf16 a, b, c, d;
            split1(p0, a, c); split1(p1, b, d);
            ph[j] = packbf(a, b); pl[j] = packbf(c, d);
            split1(p2, a, c); split1(p3, b, d);
            ph2[j] = packbf(a, b); pl2[j] = packbf(c, d);
        }
        sum0 += __shfl_xor_sync(0xffffffffu, sum0, 1);
        sum0 += __shfl_xor_sync(0xffffffffu, sum0, 2);
        sum1 += __shfl_xor_sync(0xffffffffu, sum1, 1);
        sum1 += __shfl_xor_sync(0xffffffffu, sum1, 2);
        l0 = l0 * f0 + sum0;
        l1 = l1 * f1 + sum1;
#pragma unroll
        for (int j = 0; j < 16; j++) {
            o[j][0] *= f0; o[j][1] *= f0; o[j][2] *= f1; o[j][3] *= f1;
        }

        // ---- O += P V (split 3-term) ----
#pragma unroll
        for (int kt = 0; kt < 4; kt++) {
            unsigned ahp[4] = {ph[2 * kt], ph2[2 * kt], ph[2 * kt + 1], ph2[2 * kt + 1]};
            unsigned alp[4] = {pl[2 * kt], pl2[2 * kt], pl[2 * kt + 1], pl2[2 * kt + 1]};
#pragma unroll
            for (int nv = 0; nv < 8; nv++) {
                int r = kt * 16 + (lane & 15), c = nv * 2 + (lane >> 4);
                int pc = c ^ (r & 7);
                unsigned off = (unsigned)(r * 256 + pc * 16);
                unsigned tb[4], tl[4];
                ldm4t(tb, aVh + off);
                ldm4t(tl, aVl + off);
                unsigned bh0[2] = {tb[0], tb[1]}, bh1[2] = {tb[2], tb[3]};
                unsigned bl0[2] = {tl[0], tl[1]}, bl1[2] = {tl[2], tl[3]};
                mma16816(o[nv * 2], ahp, bh0);
                mma16816(o[nv * 2], ahp, bl0);
                mma16816(o[nv * 2], alp, bh0);
                mma16816(o[nv * 2 + 1], ahp, bh1);
                mma16816(o[nv * 2 + 1], ahp, bl1);
                mma16816(o[nv * 2 + 1], alp, bh1);
            }
        }
    }

    // ---- epilogue: normalize + split-store ----
    float il0 = 1.f / l0, il1 = 1.f / l1;
    int r0 = m0 + wm + (lane >> 2);
#pragma unroll
    for (int j = 0; j < 16; j++) {
        int dv = j * 8 + (lane & 3) * 2;
        bf16 a, b, c, d;
        split1(o[j][0] * il0, a, c);
        split1(o[j][1] * il0, b, d);
        size_t off = (size_t)r0 * (NH * DV) + h * DV + dv;
        *(__nv_bfloat162*)(attn_h + off) = __nv_bfloat162(a, b);
        *(__nv_bfloat162*)(attn_l + off) = __nv_bfloat162(c, d);
        split1(o[j][2] * il1, a, c);
        split1(o[j][3] * il1, b, d);
        off += (size_t)8 * (NH * DV);
        *(__nv_bfloat162*)(attn_h + off) = __nv_bfloat162(a, b);
        *(__nv_bfloat162*)(attn_l + off) = __nv_bfloat162(c, d);
    }
}

// ---------------------------------------------------------------------------
// Launch
// ---------------------------------------------------------------------------
static inline void launch_split(const float* x, bf16* hi, bf16* lo, int n) {
    int n4 = n / 4;
    split_kernel<<<(n4 + 255) / 256, 256>>>(x, hi, lo, n4);
}

extern "C" void kernel_launch(void* const* d_in, const int* in_sizes, int n_in,
                              void* d_out, int out_size)
{
    const int*   positions = (const int*)  d_in[0];
    const float* hidden    = (const float*)d_in[1];
    const float* scaling   = (const float*)d_in[2];
    const float* w_q_a     = (const float*)d_in[3];
    const float* q_a_ln_w  = (const float*)d_in[4];
    const float* w_q_b     = (const float*)d_in[5];
    const float* w_kv_a    = (const float*)d_in[6];
    const float* kv_a_ln_w = (const float*)d_in[7];
    const float* w_kv_b    = (const float*)d_in[8];
    const float* w_o       = (const float*)d_in[9];
    const float* cs_cache  = (const float*)d_in[10];
    float* out = (float*)d_out;

    bf16 *Hh, *Hl, *Wqa_h, *Wqa_l, *Wkva_h, *Wkva_l, *Wqb_h, *Wqb_l;
    bf16 *Wkvb_h, *Wkvb_l, *Wo_h, *Wo_l, *qa_h, *qa_l, *kvan_h, *kvan_l;
    bf16 *qhp, *qlp, *khp, *klp, *vhp, *vlp, *attn_h, *attn_l;
    float *qa, *latent, *qb, *kv;
    cudaGetSymbolAddress((void**)&Hh, g_Hh);       cudaGetSymbolAddress((void**)&Hl, g_Hl);
    cudaGetSymbolAddress((void**)&Wqa_h, g_Wqa_h); cudaGetSymbolAddress((void**)&Wqa_l, g_Wqa_l);
    cudaGetSymbolAddress((void**)&Wkva_h, g_Wkva_h); cudaGetSymbolAddress((void**)&Wkva_l, g_Wkva_l);
    cudaGetSymbolAddress((void**)&Wqb_h, g_Wqb_h); cudaGetSymbolAddress((void**)&Wqb_l, g_Wqb_l);
    cudaGetSymbolAddress((void**)&Wkvb_h, g_Wkvb_h); cudaGetSymbolAddress((void**)&Wkvb_l, g_Wkvb_l);
    cudaGetSymbolAddress((void**)&Wo_h, g_Wo_h);   cudaGetSymbolAddress((void**)&Wo_l, g_Wo_l);
    cudaGetSymbolAddress((void**)&qa_h, g_qa_h);   cudaGetSymbolAddress((void**)&qa_l, g_qa_l);
    cudaGetSymbolAddress((void**)&kvan_h, g_kvan_h); cudaGetSymbolAddress((void**)&kvan_l, g_kvan_l);
    cudaGetSymbolAddress((void**)&qhp, g_qh); cudaGetSymbolAddress((void**)&qlp, g_ql);
    cudaGetSymbolAddress((void**)&khp, g_kh); cudaGetSymbolAddress((void**)&klp, g_kl);
    cudaGetSymbolAddress((void**)&vhp, g_vh); cudaGetSymbolAddress((void**)&vlp, g_vl);
    cudaGetSymbolAddress((void**)&attn_h, g_attn_h); cudaGetSymbolAddress((void**)&attn_l, g_attn_l);
    cudaGetSymbolAddress((void**)&qa, g_qa);
    cudaGetSymbolAddress((void**)&latent, g_latent);
    cudaGetSymbolAddress((void**)&qb, g_q);
    cudaGetSymbolAddress((void**)&kv, g_kv);

    cudaFuncSetAttribute(mma_gemm_kernel, cudaFuncAttributeMaxDynamicSharedMemorySize,
                         NSTAGE * STAGE_B);
    cudaFuncSetAttribute(flash_mma_kernel, cudaFuncAttributeMaxDynamicSharedMemorySize,
                         FLASH_SMEM);

    // 1. split inputs + weights
    launch_split(hidden, Hh, Hl, T_TOK * HID);
    launch_split(w_q_a, Wqa_h, Wqa_l, HID * Q_RANK);
    launch_split(w_kv_a, Wkva_h, Wkva_l, HID * KV_A_OUT);
    launch_split(w_q_b, Wqb_h, Wqb_l, Q_RANK * NH * DQK);
    launch_split(w_kv_b, Wkvb_h, Wkvb_l, KV_RANK * NH * KV_OUT);
    launch_split(w_o, Wo_h, Wo_l, NH * DV * HID);

    const dim3 blk(256);
    const int MT = T_TOK / CBM;  // 24

    // 2. qa = hidden @ w_q_a
    mma_gemm_kernel<<<dim3(Q_RANK / CBN, MT), blk, NSTAGE * STAGE_B>>>(
        Hh, Hl, Wqa_h, Wqa_l, qa, T_TOK, Q_RANK, HID);
    // 3. latent = hidden @ w_kv_a
    mma_gemm_kernel<<<dim3((KV_A_OUT + CBN - 1) / CBN, MT), blk, NSTAGE * STAGE_B>>>(
        Hh, Hl, Wkva_h, Wkva_l, latent, T_TOK, KV_A_OUT, HID);
    // 4. rmsnorm + split
    rmsnorm_split_kernel<<<T_TOK, 256>>>(qa, q_a_ln_w, qa_h, qa_l, Q_RANK, Q_RANK);
    rmsnorm_split_kernel<<<T_TOK, 256>>>(latent, kv_a_ln_w, kvan_h, kvan_l, KV_RANK, KV_A_OUT);
    // 5. q = qa_n @ w_q_b
    mma_gemm_kernel<<<dim3((NH * DQK) / CBN, MT), blk, NSTAGE * STAGE_B>>>(
        qa_h, qa_l, Wqb_h, Wqb_l, qb, T_TOK, NH * DQK, Q_RANK);
    // 6. kv = kvan @ w_kv_b
    mma_gemm_kernel<<<dim3((NH * KV_OUT) / CBN, MT), blk, NSTAGE * STAGE_B>>>(
        kvan_h, kvan_l, Wkvb_h, Wkvb_l, kv, T_TOK, NH * KV_OUT, KV_RANK);
    // 7. rope + scale folding + head-major splits
    prep_kernel<<<T_TOK, 256>>>(positions, cs_cache, scaling, latent, qb, kv,
                                qhp, qlp, khp, klp, vhp, vlp);
    // 8. tensor-core flash attention
    flash_mma_kernel<<<dim3(T_TOK / AM, NH), 256, FLASH_SMEM>>>(
        qhp, qlp, khp, klp, vhp, vlp, attn_h, attn_l);
    // 9. out = attn @ w_o
    mma_gemm_kernel<<<dim3(HID / CBN, MT), blk, NSTAGE * STAGE_B>>>(
        attn_h, attn_l, Wo_h, Wo_l, out, T_TOK, HID, NH * DV);
}